// round 15
// baseline (speedup 1.0000x reference)
#include <cuda_runtime.h>
#include <cuda_bf16.h>

#define NPSI 256
#define MM 8
#define KK 4

typedef unsigned long long u64c;   // carrier for packed f32x2

__device__ __forceinline__ u64c f2pk(float lo, float hi) {
    u64c r;
    asm("mov.b64 %0, {%1, %2};"
        : "=l"(r) : "r"(__float_as_uint(lo)), "r"(__float_as_uint(hi)));
    return r;
}
__device__ __forceinline__ void f2unpk(u64c v, float& lo, float& hi) {
    unsigned int a, b;
    asm("mov.b64 {%0, %1}, %2;" : "=r"(a), "=r"(b) : "l"(v));
    lo = __uint_as_float(a);
    hi = __uint_as_float(b);
}
__device__ __forceinline__ u64c f2fma(u64c a, u64c b, u64c c) {
    u64c d;
    asm("fma.rn.f32x2 %0, %1, %2, %3;" : "=l"(d) : "l"(a), "l"(b), "l"(c));
    return d;
}
__device__ __forceinline__ u64c f2add(u64c a, u64c b) {
    u64c d;
    asm("add.rn.f32x2 %0, %1, %2;" : "=l"(d) : "l"(a), "l"(b));
    return d;
}
// raw EX2 (what __expf bottoms out in, minus its extra log2e multiply)
__device__ __forceinline__ float fex2(float a) {
    float r;
    asm("ex2.approx.f32 %0, %1;" : "=f"(r) : "f"(a));
    return r;
}

// K = sqrt(log2(e)/2):  exp(-0.5*y^2) == 2^(-(K*y)^2)
#define KEXP 0.84932184f

__global__ __launch_bounds__(256, 2)
void eikonal_field_kernel(const float* __restrict__ t_ptr,
                          const float* __restrict__ psi,
                          const float* __restrict__ theta,
                          const float* __restrict__ varphi,
                          const float* __restrict__ q_vals,
                          const float* __restrict__ theta0,
                          const float* __restrict__ omega,
                          const float* __restrict__ psi0,
                          const float* __restrict__ psi_scale,
                          const float* __restrict__ alpha_scale,
                          const float* __restrict__ gh,
                          const int*   __restrict__ n_arr,
                          float* __restrict__ out,
                          int N, int half)
{
    __shared__ float sq[NPSI];
    __shared__ float sm[NPSI];                 // FD slopes (jnp.gradient), prebuilt
    __shared__ float s_th0[MM], s_p0[MM], s_ips[MM], s_ias[MM], s_nf[MM];
    __shared__ float s_ipsK[MM], s_iasK[MM];   // K/psi_scale, K/alpha_scale
    __shared__ float s_omt[MM], s_nfc[MM];     // omega*t/2pi (uniform t!), n/2pi
    // Packed Gauss-Hermite coefficient table, folded at load time (see R5 notes)
    __shared__ u64c spk[MM * 12];

    const float INV_2PI_H = 0.159154943091895335769f;

    const int tid = threadIdx.x;
    for (int j = tid; j < NPSI; j += blockDim.x) {
        sq[j] = q_vals[j];
        sm[j] = (j == 0)        ? (q_vals[1] - q_vals[0])
              : (j == NPSI - 1) ? (q_vals[NPSI - 1] - q_vals[NPSI - 2])
                                : 0.5f * (q_vals[j + 1] - q_vals[j - 1]);
    }
    if (tid < MM) {
        s_th0[tid]  = theta0[tid];
        s_p0[tid]   = psi0[tid];
        const float ips = 1.0f / psi_scale[tid];
        const float ias = 1.0f / alpha_scale[tid];
        s_ips[tid]  = ips;
        s_ias[tid]  = ias;
        s_ipsK[tid] = ips * KEXP;
        s_iasK[tid] = ias * KEXP;
        const float nf = (float)n_arr[tid];
        s_nf[tid]   = nf;
        s_nfc[tid]  = nf * INV_2PI_H;
        s_omt[tid]  = omega[tid] * INV_2PI_H * t_ptr[0];
    }
    if (tid < MM * 12) {
        const int m    = tid / 12;
        const int r    = tid % 12;
        const int pair = r / 6;
        const int cs   = r % 6;
        const int cc0  = pair * 2;
        const float* c = gh + m * 24;
        const float* a = c + cc0 * 6;
        const float* b = c + (cc0 + 1) * 6;
        float lo, hi;
        switch (cs) {
            case 0: lo = a[0] - 2.f * a[3] - 2.f * a[5];
                    hi = b[0] - 2.f * b[3] - 2.f * b[5]; break;   // Q0
            case 1: lo = a[1];        hi = b[1];        break;    // c1
            case 2: lo = 4.f * a[3];  hi = 4.f * b[3];  break;    // Q3
            case 3: lo = a[2];        hi = b[2];        break;    // c2
            case 4: lo = a[4];        hi = b[4];        break;    // c4
            default: lo = 4.f * a[5]; hi = 4.f * b[5];  break;    // C
        }
        spk[tid] = f2pk(lo, hi);
    }
    __syncthreads();

    const int i = blockIdx.x * blockDim.x + tid;
    if (i >= half) return;
    const int  i2   = i + half;
    const bool has2 = (i2 < N);
    const int  i2c  = has2 ? i2 : i;     // safe index for loads

    // ---- particle A and B inputs ----
    const float psA = psi[i],    thA = theta[i],    vpA = varphi[i];
    const float psB = psi[i2c],  thB = theta[i2c],  vpB = varphi[i2c];

    const float TWO_PI = 6.283185307179586476925f;

    // ---- cubic Hermite interp of q for both particles ----
    float qA, qB;
    {
        float u = psA * 255.0f;
        int j = (int)floorf(u);
        j = min(max(j, 0), NPSI - 2);
        const float s  = u - (float)j;
        const float s2 = s * s, s3 = s2 * s;
        qA = (2.f*s3 - 3.f*s2 + 1.f) * sq[j] + (s3 - 2.f*s2 + s) * sm[j]
           + (-2.f*s3 + 3.f*s2) * sq[j+1] + (s3 - s2) * sm[j+1];
    }
    {
        float u = psB * 255.0f;
        int j = (int)floorf(u);
        j = min(max(j, 0), NPSI - 2);
        const float s  = u - (float)j;
        const float s2 = s * s, s3 = s2 * s;
        qB = (2.f*s3 - 3.f*s2 + 1.f) * sq[j] + (s3 - 2.f*s2 + s) * sm[j]
           + (-2.f*s3 + 3.f*s2) * sq[j+1] + (s3 - s2) * sm[j+1];
    }
    const float q2piA = qA * TWO_PI;
    const float q2piB = qB * TWO_PI;

    u64c acc01A = 0ull, acc23A = 0ull;
    u64c acc01B = 0ull, acc23B = 0ull;

    #pragma unroll
    for (int m = 0; m < MM; ++m) {
        const u64c* pm = &spk[m * 12];
        const float p0m = s_p0[m],  ipsm = s_ips[m], ipsKm = s_ipsK[m];
        const float iasm = s_ias[m], iasKm = s_iasK[m];
        const float th0m = s_th0[m], nfcm = s_nfc[m], omtm = s_omt[m], nfm = s_nf[m];

        // ---- per-particle x-dependent coefficients (coeff LDS shared!) ----
        const float dpsA = psA - p0m,  dpsB = psB - p0m;
        const float xA = dpsA * ipsm,  xB = dpsB * ipsm;
        const float xwA = dpsA * ipsKm, xwB = dpsB * ipsKm;
        const float gxA = fex2(-xwA * xwA);
        const float gxB = fex2(-xwB * xwB);

        const u64c xxA = f2pk(xA, xA), x22A = f2pk(xA * xA, xA * xA);
        const u64c xxB = f2pk(xB, xB), x22B = f2pk(xB * xB, xB * xB);
        const u64c A01A = f2fma(pm[2], x22A, f2fma(pm[1], xxA, pm[0]));
        const u64c B01A = f2fma(pm[4], xxA, pm[3]);
        const u64c A23A = f2fma(pm[8], x22A, f2fma(pm[7], xxA, pm[6]));
        const u64c B23A = f2fma(pm[10], xxA, pm[9]);
        const u64c A01B = f2fma(pm[2], x22B, f2fma(pm[1], xxB, pm[0]));
        const u64c B01B = f2fma(pm[4], xxB, pm[3]);
        const u64c A23B = f2fma(pm[8], x22B, f2fma(pm[7], xxB, pm[6]));
        const u64c B23B = f2fma(pm[10], xxB, pm[9]);
        const u64c C01 = pm[5], C23 = pm[11];

        const float qdthA = qA * (thA - th0m);
        const float qdthB = qB * (thB - th0m);
        u64c yyA = f2pk(qdthA * iasm, qdthA * iasm);
        u64c yyB = f2pk(qdthB * iasm, qdthB * iasm);
        const u64c dypkA = f2pk(q2piA * iasm, q2piA * iasm);
        const u64c dypkB = f2pk(q2piB * iasm, q2piB * iasm);
        float wA = qdthA * iasKm,  dwA = q2piA * iasKm;
        float wB = qdthB * iasKm,  dwB = q2piB * iasKm;

        // phase in cycles (see R8/R9 notes)
        float prA = fmaf(nfcm, qdthA, fmaf(-nfcm, vpA, omtm));
        float prB = fmaf(nfcm, qdthB, fmaf(-nfcm, vpB, omtm));
        prA -= rintf(prA);
        prB -= rintf(prB);
        float cpA, spA, cpB, spB;
        __sincosf(TWO_PI * prA, &spA, &cpA);
        __sincosf(TWO_PI * prB, &spB, &cpB);

        const float rA = nfm * qA, rB = nfm * qB;
        const float rrA = rA - rintf(rA), rrB = rB - rintf(rB);
        float cdA, sdA, cdB, sdB;
        __sincosf(TWO_PI * rrA, &sdA, &cdA);
        __sincosf(TWO_PI * rrB, &sdB, &cdB);

        float uphA = gxA * cpA, vphA = gxA * spA;
        float uphB = gxB * cpB, vphB = gxB * spB;

        #pragma unroll
        for (int k = 0; k < KK; ++k) {
            const float eA = fex2(-wA * wA);   // no recurrence: dy can be ~100,
            const float eB = fex2(-wB * wB);   // underflow makes it non-monotone
            const u64c gcsA = f2pk(eA * uphA, eA * vphA);
            const u64c gcsB = f2pk(eB * uphB, eB * vphB);
            const u64c p01A = f2fma(f2fma(C01, yyA, B01A), yyA, A01A);
            const u64c p23A = f2fma(f2fma(C23, yyA, B23A), yyA, A23A);
            const u64c p01B = f2fma(f2fma(C01, yyB, B01B), yyB, A01B);
            const u64c p23B = f2fma(f2fma(C23, yyB, B23B), yyB, A23B);
            acc01A = f2fma(p01A, gcsA, acc01A);
            acc23A = f2fma(p23A, gcsA, acc23A);
            acc01B = f2fma(p01B, gcsB, acc01B);
            acc23B = f2fma(p23B, gcsB, acc23B);
            if (k < KK - 1) {
                const float unA = fmaf(uphA, cdA, -(vphA * sdA));
                vphA = fmaf(vphA, cdA, uphA * sdA);
                uphA = unA;
                const float unB = fmaf(uphB, cdB, -(vphB * sdB));
                vphB = fmaf(vphB, cdB, uphB * sdB);
                uphB = unB;
                yyA = f2add(yyA, dypkA);
                yyB = f2add(yyB, dypkB);
                wA += dwA;
                wB += dwB;
            }
        }
    }

    float a0, a1, a2, a3;
    f2unpk(acc01A, a0, a1);
    f2unpk(acc23A, a2, a3);
    out[i]     = a0 - a1;   // phi
    out[N + i] = a2 - a3;   // apar
    if (has2) {
        f2unpk(acc01B, a0, a1);
        f2unpk(acc23B, a2, a3);
        out[i2]     = a0 - a1;
        out[N + i2] = a2 - a3;
    }
}

extern "C" void kernel_launch(void* const* d_in, const int* in_sizes, int n_in,
                              void* d_out, int out_size)
{
    // metadata order: t, psi, theta, varphi, q_vals, aoff_vals, theta0, omega,
    //                 psi0, psi_scale, alpha_scale, gh_coefs, n
    const float* t           = (const float*)d_in[0];
    const float* psi         = (const float*)d_in[1];
    const float* theta       = (const float*)d_in[2];
    const float* varphi      = (const float*)d_in[3];
    const float* q_vals      = (const float*)d_in[4];
    // d_in[5] = aoff_vals: provably cancels out of both outputs
    const float* theta0      = (const float*)d_in[6];
    const float* omega       = (const float*)d_in[7];
    const float* psi0        = (const float*)d_in[8];
    const float* psi_scale   = (const float*)d_in[9];
    const float* alpha_scale = (const float*)d_in[10];
    const float* gh_coefs    = (const float*)d_in[11];
    const int*   n_arr       = (const int*)d_in[12];

    const int N = in_sizes[1];
    const int half = (N + 1) / 2;
    const int threads = 256;
    const int blocks = (half + threads - 1) / threads;
    eikonal_field_kernel<<<blocks, threads>>>(t, psi, theta, varphi, q_vals,
                                              theta0, omega, psi0, psi_scale,
                                              alpha_scale, gh_coefs, n_arr,
                                              (float*)d_out, N, half);
}